// round 12
// baseline (speedup 1.0000x reference)
#include <cuda_runtime.h>
#include <cuda_bf16.h>
#include <cstdint>
#include <math.h>

// Problem shape (fixed)
#define Bp 4
#define Tp 2048
#define Cp 2048
#define Hp 16
#define Dp 128
#define BHp (Bp*Hp)        // 64
#define BTp (Bp*Tp)        // 8192
#define SCALE 0.08838834764831845f  // 1/sqrt(128)

// Scratch (device globals; allocation-free per harness rules)
__device__ float g_q [BHp * Tp * Dp];   // [B,H,T,d]
__device__ float g_k [BHp * Tp * Dp];
__device__ float g_v [BHp * Tp * Dp];
__device__ float g_ao[BTp * Cp];        // attention out, [B,T,C] (tf32-rounded)
__device__ float g_xc[BTp * Cp];        // x, tf32-rounded
__device__ float g_wa[3 * Cp * Cp];     // W_attn, tf32-rounded
__device__ float g_wp[Cp * Cp];         // W_proj, tf32-rounded

__device__ __forceinline__ uint32_t f2tf32(float x) {
    uint32_t r;
    asm("cvt.rna.tf32.f32 %0, %1;" : "=r"(r) : "f"(x));
    return r;
}

__device__ __forceinline__ void mma_tf32(float* d, const uint32_t* a, const uint32_t* b) {
    asm volatile(
        "mma.sync.aligned.m16n8k8.row.col.f32.tf32.tf32.f32 "
        "{%0,%1,%2,%3}, {%4,%5,%6,%7}, {%8,%9}, {%0,%1,%2,%3};"
        : "+f"(d[0]), "+f"(d[1]), "+f"(d[2]), "+f"(d[3])
        : "r"(a[0]), "r"(a[1]), "r"(a[2]), "r"(a[3]), "r"(b[0]), "r"(b[1]));
}

__device__ __forceinline__ void ldsm_x4(uint32_t* r, uint32_t addr) {
    asm volatile("ldmatrix.sync.aligned.m8n8.x4.shared.b16 {%0,%1,%2,%3}, [%4];"
                 : "=r"(r[0]), "=r"(r[1]), "=r"(r[2]), "=r"(r[3]) : "r"(addr));
}

__device__ __forceinline__ void cp16(uint32_t saddr, const void* gaddr) {
    asm volatile("cp.async.cg.shared.global [%0], [%1], 16;"
                 :: "r"(saddr), "l"(gaddr) : "memory");
}
#define CP_COMMIT() asm volatile("cp.async.commit_group;" ::: "memory")
#define CP_WAIT(N)  asm volatile("cp.async.wait_group %0;" :: "n"(N) : "memory")

// ===========================================================================
// Elementwise tf32 rounding pre-pass (float4 vectorized)
// ===========================================================================
__global__ void cvt_tf32_kernel(const float4* __restrict__ in,
                                float4* __restrict__ out, int n4)
{
    int i = blockIdx.x * blockDim.x + threadIdx.x;
    if (i < n4) {
        float4 v = in[i];
        v.x = __uint_as_float(f2tf32(v.x));
        v.y = __uint_as_float(f2tf32(v.y));
        v.z = __uint_as_float(f2tf32(v.z));
        v.w = __uint_as_float(f2tf32(v.w));
        out[i] = v;
    }
}

// ===========================================================================
// tf32 mma.sync GEMM:  C[m][n] = sum_k A[m][k]*B[n][k]   (NT, both K-major)
// Inputs pre-rounded to tf32. 4-stage cp.async ring, one barrier per iter,
// ldmatrix.x4 fragments. 128 threads (4 warps 2x2), warp tile 64x64.
// EPI=0: row-major store. EPI=1: qkv scatter to [B,H,T,d].
// ===========================================================================
#define BM 128
#define BN 128
#define BK 16
#define KP 20                      // row stride (uint32) -> 80B rows, LDSM conflict-free
#define NSTG 4
#define STG_U32 (BM*KP)
#define STG_BYTES (STG_U32*4)      // 10240
#define GEMM_SMEM (2*NSTG*STG_BYTES)  // 81920

template <int EPI>
__global__ void __launch_bounds__(128, 2)
gemm_mma(const float* __restrict__ A, const float* __restrict__ B,
         float* __restrict__ Cq, float* __restrict__ Ck, float* __restrict__ Cv,
         int M, int N, int K)
{
    extern __shared__ __align__(16) uint32_t smg[];

    const int tid = threadIdx.x;
    const int lane = tid & 31;
    const int wid = tid >> 5;            // 0..3
    const int wm = (wid & 1) * 64;
    const int wn = (wid >> 1) * 64;
    const int m0 = blockIdx.y * BM;
    const int n0 = blockIdx.x * BN;

    float acc[4][8][4];
#pragma unroll
    for (int i = 0; i < 4; i++)
#pragma unroll
        for (int j = 0; j < 8; j++)
#pragma unroll
            for (int q = 0; q < 4; q++) acc[i][j][q] = 0.f;

    const int NK = K / BK;

    const int cr = tid >> 2;             // base row (x4 via +32*i)
    const int cc = tid & 3;              // 16B chunk within row
    const uint32_t as_sm = (uint32_t)__cvta_generic_to_shared(&smg[0]);
    const uint32_t bs_sm = as_sm + NSTG * STG_BYTES;

    // ldmatrix per-lane addresses (stage 0)
    const uint32_t a_addr = as_sm + (((wm + (lane & 15)) * KP + ((lane >> 4) << 2)) << 2);
    const uint32_t b_addr = bs_sm + (((wn + ((lane >> 4) << 3) + (lane & 7)) * KP
                                      + (((lane >> 3) & 1) << 2)) << 2);

    const float* Agp = A + (long)(m0 + cr) * K + cc * 4;
    const float* Bgp = B + (long)(n0 + cr) * K + cc * 4;
    const long rowK32 = (long)32 * K;

#define ISSUE_STAGE(stg, kt_) do {                                          \
        const uint32_t asx = as_sm + (stg) * STG_BYTES + ((cr * KP + cc * 4) << 2); \
        const uint32_t bsx = bs_sm + (stg) * STG_BYTES + ((cr * KP + cc * 4) << 2); \
        const float* ag = Agp + (kt_) * BK;                                 \
        const float* bg = Bgp + (kt_) * BK;                                 \
        _Pragma("unroll")                                                   \
        for (int i_ = 0; i_ < 4; i_++) {                                    \
            cp16(asx + i_ * (32 * KP * 4), ag + i_ * rowK32);               \
            cp16(bsx + i_ * (32 * KP * 4), bg + i_ * rowK32);               \
        }                                                                   \
        CP_COMMIT();                                                        \
    } while (0)

    // prologue: stages 0..NSTG-2
    ISSUE_STAGE(0, 0);
    ISSUE_STAGE(1, 1);
    ISSUE_STAGE(2, 2);

    for (int kt = 0; kt < NK; kt++) {
        const int s = kt & (NSTG - 1);
        CP_WAIT(NSTG - 2);               // stage kt complete
        __syncthreads();                 // stage (kt-1) fully consumed by all warps

        if (kt + NSTG - 1 < NK) {
            ISSUE_STAGE((kt + NSTG - 1) & (NSTG - 1), kt + NSTG - 1);
        } else {
            CP_COMMIT();                 // keep group count consistent in tail
        }

        const uint32_t as_s = a_addr + s * STG_BYTES;
        const uint32_t bs_s = b_addr + s * STG_BYTES;
#pragma unroll
        for (int ks = 0; ks < 2; ks++) {
            const uint32_t kb = ks * 32;
            uint32_t af[4][4], bf[8][2];
#pragma unroll
            for (int i = 0; i < 4; i++)
                ldsm_x4(af[i], as_s + kb + i * (16 * KP * 4));
#pragma unroll
            for (int jj = 0; jj < 4; jj++)
                ldsm_x4(&bf[jj * 2][0], bs_s + kb + jj * (16 * KP * 4));
#pragma unroll
            for (int i = 0; i < 4; i++)
#pragma unroll
                for (int j = 0; j < 8; j++)
                    mma_tf32(acc[i][j], af[i], bf[j]);
        }
    }
#undef ISSUE_STAGE

    const int ar = lane >> 2;
    const int ac = lane & 3;

#pragma unroll
    for (int i = 0; i < 4; i++) {
        const int mrow0 = m0 + wm + i * 16 + ar;
#pragma unroll
        for (int j = 0; j < 8; j++) {
            const int n = n0 + wn + j * 8 + ac * 2;
            if (EPI == 0) {
                float* d0 = Cq + (long)mrow0 * N + n;
                float* d1 = Cq + (long)(mrow0 + 8) * N + n;
                *(float2*)d0 = make_float2(acc[i][j][0], acc[i][j][1]);
                *(float2*)d1 = make_float2(acc[i][j][2], acc[i][j][3]);
            } else {
                const int which = n >> 11;
                const int rem = n & 2047;
                const int h = rem >> 7, dd = rem & 127;
                float* base = (which == 0) ? Cq : (which == 1) ? Ck : Cv;
                const int b0_ = mrow0 >> 11, t0 = mrow0 & 2047;
                const int b1_ = (mrow0 + 8) >> 11, t1 = (mrow0 + 8) & 2047;
                float* d0 = base + (((long)(b0_ * Hp + h) * Tp + t0) * Dp + dd);
                float* d1 = base + (((long)(b1_ * Hp + h) * Tp + t1) * Dp + dd);
                *(float2*)d0 = make_float2(acc[i][j][0], acc[i][j][1]);
                *(float2*)d1 = make_float2(acc[i][j][2], acc[i][j][3]);
            }
        }
    }
}

// ===========================================================================
// Tensor-core causal flash attention (tf32 mma.sync).
// Epilogue stores tf32-rounded fp32 (so the proj GEMM can skip conversion).
// ===========================================================================
#define AQ_STR 132
#define KV_STR 132
#define P_STR  68
#define ATTN2_SMEM ((128*AQ_STR + 64*KV_STR + 64*KV_STR + 8*16*P_STR) * 4)

__global__ void __launch_bounds__(256)
attn_tc(const float* __restrict__ Qg, const float* __restrict__ Kg,
        const float* __restrict__ Vg, float* __restrict__ Og)
{
    extern __shared__ uint32_t sm[];
    uint32_t* Qs = sm;                       // [128][132]
    uint32_t* Ks = Qs + 128 * AQ_STR;        // [64][132]
    uint32_t* Vs = Ks + 64 * KV_STR;         // [64][132]
    uint32_t* Ps = Vs + 64 * KV_STR;         // [8][16][68]

    const int tid = threadIdx.x;
    const int lane = tid & 31;
    const int w = tid >> 5;
    const int g = lane >> 2;
    const int t4 = lane & 3;
    const int qt = gridDim.x - 1 - blockIdx.x;
    const int bh = blockIdx.y;
    const int q0 = qt * 128;
    const long base = (long)bh * Tp * Dp;
    uint32_t* Pw = Ps + w * 16 * P_STR;

    for (int i = tid; i < 128 * 32; i += 256) {
        int r = i >> 5, c4 = i & 31;
        float4 v = *(const float4*)(Qg + base + (long)(q0 + r) * Dp + c4 * 4);
        uint4 u;
        u.x = f2tf32(v.x); u.y = f2tf32(v.y); u.z = f2tf32(v.z); u.w = f2tf32(v.w);
        *(uint4*)&Qs[r * AQ_STR + c4 * 4] = u;
    }

    float oacc[16][4];
#pragma unroll
    for (int i = 0; i < 16; i++)
#pragma unroll
        for (int q = 0; q < 4; q++) oacc[i][q] = 0.f;
    float m_lo = -1e30f, m_hi = -1e30f, l_lo = 0.f, l_hi = 0.f;

    const int row_lo = q0 + w * 16 + g;
    const int row_hi = row_lo + 8;
    const int njt = qt * 2 + 2;

    for (int j = 0; j < njt; j++) {
        __syncthreads();
        for (int i = tid; i < 64 * 32; i += 256) {
            int r = i >> 5, c4 = i & 31;
            float4 kv = *(const float4*)(Kg + base + (long)(j * 64 + r) * Dp + c4 * 4);
            float4 vv = *(const float4*)(Vg + base + (long)(j * 64 + r) * Dp + c4 * 4);
            uint4 uk, uv;
            uk.x = f2tf32(kv.x); uk.y = f2tf32(kv.y); uk.z = f2tf32(kv.z); uk.w = f2tf32(kv.w);
            uv.x = f2tf32(vv.x); uv.y = f2tf32(vv.y); uv.z = f2tf32(vv.z); uv.w = f2tf32(vv.w);
            *(uint4*)&Ks[r * KV_STR + c4 * 4] = uk;
            *(uint4*)&Vs[r * KV_STR + c4 * 4] = uv;
        }
        __syncthreads();

        float sf[8][4];
#pragma unroll
        for (int n = 0; n < 8; n++)
#pragma unroll
            for (int q = 0; q < 4; q++) sf[n][q] = 0.f;

#pragma unroll 4
        for (int kc = 0; kc < 16; kc++) {
            uint32_t af[4];
            const uint32_t* qrow = Qs + (w * 16) * AQ_STR + kc * 8;
            af[0] = qrow[g * AQ_STR + t4];
            af[1] = qrow[(g + 8) * AQ_STR + t4];
            af[2] = qrow[g * AQ_STR + t4 + 4];
            af[3] = qrow[(g + 8) * AQ_STR + t4 + 4];
#pragma unroll
            for (int n = 0; n < 8; n++) {
                uint32_t bf[2];
                const uint32_t* krow = Ks + (n * 8 + g) * KV_STR + kc * 8;
                bf[0] = krow[t4];
                bf[1] = krow[t4 + 4];
                mma_tf32(sf[n], af, bf);
            }
        }

        if (j * 64 + 63 <= q0 + w * 16) {
#pragma unroll
            for (int n = 0; n < 8; n++)
#pragma unroll
                for (int q = 0; q < 4; q++) sf[n][q] *= SCALE;
        } else {
#pragma unroll
            for (int n = 0; n < 8; n++) {
                const int col = j * 64 + n * 8 + 2 * t4;
                sf[n][0] = (col     <= row_lo) ? sf[n][0] * SCALE : -1e30f;
                sf[n][1] = (col + 1 <= row_lo) ? sf[n][1] * SCALE : -1e30f;
                sf[n][2] = (col     <= row_hi) ? sf[n][2] * SCALE : -1e30f;
                sf[n][3] = (col + 1 <= row_hi) ? sf[n][3] * SCALE : -1e30f;
            }
        }

        float tl = -1e30f, th = -1e30f;
#pragma unroll
        for (int n = 0; n < 8; n++) {
            tl = fmaxf(tl, fmaxf(sf[n][0], sf[n][1]));
            th = fmaxf(th, fmaxf(sf[n][2], sf[n][3]));
        }
        tl = fmaxf(tl, __shfl_xor_sync(0xffffffffu, tl, 1));
        tl = fmaxf(tl, __shfl_xor_sync(0xffffffffu, tl, 2));
        th = fmaxf(th, __shfl_xor_sync(0xffffffffu, th, 1));
        th = fmaxf(th, __shfl_xor_sync(0xffffffffu, th, 2));
        const float mn_lo = fmaxf(m_lo, tl);
        const float mn_hi = fmaxf(m_hi, th);
        const float corr_lo = __expf(m_lo - mn_lo);
        const float corr_hi = __expf(m_hi - mn_hi);
        m_lo = mn_lo; m_hi = mn_hi;

        float sum_lo = 0.f, sum_hi = 0.f;
#pragma unroll
        for (int n = 0; n < 8; n++) {
            float p0 = __expf(sf[n][0] - m_lo);
            float p1 = __expf(sf[n][1] - m_lo);
            float p2 = __expf(sf[n][2] - m_hi);
            float p3 = __expf(sf[n][3] - m_hi);
            sum_lo += p0 + p1;
            sum_hi += p2 + p3;
            const int pc = n * 8 + 2 * t4;
            Pw[g * P_STR + pc]           = f2tf32(p0);
            Pw[g * P_STR + pc + 1]       = f2tf32(p1);
            Pw[(g + 8) * P_STR + pc]     = f2tf32(p2);
            Pw[(g + 8) * P_STR + pc + 1] = f2tf32(p3);
        }
        sum_lo += __shfl_xor_sync(0xffffffffu, sum_lo, 1);
        sum_lo += __shfl_xor_sync(0xffffffffu, sum_lo, 2);
        sum_hi += __shfl_xor_sync(0xffffffffu, sum_hi, 1);
        sum_hi += __shfl_xor_sync(0xffffffffu, sum_hi, 2);
        l_lo = l_lo * corr_lo + sum_lo;
        l_hi = l_hi * corr_hi + sum_hi;
#pragma unroll
        for (int dt = 0; dt < 16; dt++) {
            oacc[dt][0] *= corr_lo; oacc[dt][1] *= corr_lo;
            oacc[dt][2] *= corr_hi; oacc[dt][3] *= corr_hi;
        }
        __syncwarp();

        uint32_t paf[8][4];
#pragma unroll
        for (int kc = 0; kc < 8; kc++) {
            paf[kc][0] = Pw[g * P_STR + kc * 8 + t4];
            paf[kc][1] = Pw[(g + 8) * P_STR + kc * 8 + t4];
            paf[kc][2] = Pw[g * P_STR + kc * 8 + t4 + 4];
            paf[kc][3] = Pw[(g + 8) * P_STR + kc * 8 + t4 + 4];
        }
#pragma unroll 2
        for (int dt = 0; dt < 16; dt++) {
#pragma unroll
            for (int kc = 0; kc < 8; kc++) {
                uint32_t bf[2];
                bf[0] = Vs[(kc * 8 + t4) * KV_STR + dt * 8 + g];
                bf[1] = Vs[(kc * 8 + t4 + 4) * KV_STR + dt * 8 + g];
                mma_tf32(oacc[dt], paf[kc], bf);
            }
        }
    }

    const float il_lo = 1.f / l_lo;
    const float il_hi = 1.f / l_hi;
    const int b = bh >> 4, h = bh & 15;
    float* o_lo = Og + ((long)(b * Tp + row_lo)) * Cp + h * Dp;
    float* o_hi = Og + ((long)(b * Tp + row_hi)) * Cp + h * Dp;
#pragma unroll
    for (int dt = 0; dt < 16; dt++) {
        const int col = dt * 8 + 2 * t4;
        float2 v0 = make_float2(__uint_as_float(f2tf32(oacc[dt][0] * il_lo)),
                                __uint_as_float(f2tf32(oacc[dt][1] * il_lo)));
        float2 v1 = make_float2(__uint_as_float(f2tf32(oacc[dt][2] * il_hi)),
                                __uint_as_float(f2tf32(oacc[dt][3] * il_hi)));
        *(float2*)(o_lo + col) = v0;
        *(float2*)(o_hi + col) = v1;
    }
}

// ---------------------------------------------------------------------------
extern "C" void kernel_launch(void* const* d_in, const int* in_sizes, int n_in,
                              void* d_out, int out_size)
{
    const float* x      = (const float*)d_in[0];  // [B,T,C]
    const float* W_attn = (const float*)d_in[1];  // [3C,C]
    const float* W_proj = (const float*)d_in[2];  // [C,C]
    float* out = (float*)d_out;                   // [B,T,C]

    float *pq, *pk, *pv, *pao, *pxc, *pwa, *pwp;
    cudaGetSymbolAddress((void**)&pq,  g_q);
    cudaGetSymbolAddress((void**)&pk,  g_k);
    cudaGetSymbolAddress((void**)&pv,  g_v);
    cudaGetSymbolAddress((void**)&pao, g_ao);
    cudaGetSymbolAddress((void**)&pxc, g_xc);
    cudaGetSymbolAddress((void**)&pwa, g_wa);
    cudaGetSymbolAddress((void**)&pwp, g_wp);

    cudaFuncSetAttribute(attn_tc,
                         cudaFuncAttributeMaxDynamicSharedMemorySize, ATTN2_SMEM);
    cudaFuncSetAttribute(gemm_mma<0>,
                         cudaFuncAttributeMaxDynamicSharedMemorySize, GEMM_SMEM);
    cudaFuncSetAttribute(gemm_mma<1>,
                         cudaFuncAttributeMaxDynamicSharedMemorySize, GEMM_SMEM);

    // 0) tf32 rounding pre-pass
    {
        int n4x = BTp * Cp / 4, n4a = 3 * Cp * Cp / 4, n4p = Cp * Cp / 4;
        cvt_tf32_kernel<<<(n4x + 255) / 256, 256>>>((const float4*)x,      (float4*)pxc, n4x);
        cvt_tf32_kernel<<<(n4a + 255) / 256, 256>>>((const float4*)W_attn, (float4*)pwa, n4a);
        cvt_tf32_kernel<<<(n4p + 255) / 256, 256>>>((const float4*)W_proj, (float4*)pwp, n4p);
    }
    // 1) QKV projection with scatter into [B,H,T,d]
    {
        dim3 grid(3 * Cp / BN, BTp / BM);
        gemm_mma<1><<<grid, 128, GEMM_SMEM>>>(pxc, pwa, pq, pk, pv, BTp, 3 * Cp, Cp);
    }
    // 2) tensor-core causal flash attention -> g_ao [B,T,C] (tf32-rounded)
    {
        dim3 grid(Tp / 128, BHp);
        attn_tc<<<grid, 256, ATTN2_SMEM>>>(pq, pk, pv, pao);
    }
    // 3) output projection
    {
        dim3 grid(Cp / BN, BTp / BM);
        gemm_mma<0><<<grid, 128, GEMM_SMEM>>>(pao, pwp, out, nullptr, nullptr, BTp, Cp, Cp);
    }
}

// round 13
// speedup vs baseline: 2.0169x; 2.0169x over previous
#include <cuda_runtime.h>
#include <cuda_fp16.h>
#include <cstdint>
#include <math.h>

// Problem shape (fixed)
#define Bp 4
#define Tp 2048
#define Cp 2048
#define Hp 16
#define Dp 128
#define BHp (Bp*Hp)        // 64
#define BTp (Bp*Tp)        // 8192
#define SCALE 0.08838834764831845f  // 1/sqrt(128)

// Scratch (device globals; allocation-free per harness rules)
__device__ __half g_qh [BHp * Tp * Dp];   // [B,H,T,d]
__device__ __half g_kh [BHp * Tp * Dp];
__device__ __half g_vh [BHp * Tp * Dp];
__device__ __half g_aoh[BTp * Cp];        // attention out, [B,T,C]
__device__ __half g_xh [BTp * Cp];        // x, fp16
__device__ __half g_wah[3 * Cp * Cp];     // W_attn, fp16
__device__ __half g_wph[Cp * Cp];         // W_proj, fp16

__device__ __forceinline__ void mma_f16(float* d, const uint32_t* a, const uint32_t* b) {
    asm volatile(
        "mma.sync.aligned.m16n8k16.row.col.f32.f16.f16.f32 "
        "{%0,%1,%2,%3}, {%4,%5,%6,%7}, {%8,%9}, {%0,%1,%2,%3};"
        : "+f"(d[0]), "+f"(d[1]), "+f"(d[2]), "+f"(d[3])
        : "r"(a[0]), "r"(a[1]), "r"(a[2]), "r"(a[3]), "r"(b[0]), "r"(b[1]));
}

__device__ __forceinline__ void ldsm_x4(uint32_t* r, uint32_t addr) {
    asm volatile("ldmatrix.sync.aligned.m8n8.x4.shared.b16 {%0,%1,%2,%3}, [%4];"
                 : "=r"(r[0]), "=r"(r[1]), "=r"(r[2]), "=r"(r[3]) : "r"(addr));
}
__device__ __forceinline__ void ldsm_x4_t(uint32_t* r, uint32_t addr) {
    asm volatile("ldmatrix.sync.aligned.m8n8.x4.trans.shared.b16 {%0,%1,%2,%3}, [%4];"
                 : "=r"(r[0]), "=r"(r[1]), "=r"(r[2]), "=r"(r[3]) : "r"(addr));
}

__device__ __forceinline__ void cp16(uint32_t saddr, const void* gaddr) {
    asm volatile("cp.async.cg.shared.global [%0], [%1], 16;"
                 :: "r"(saddr), "l"(gaddr) : "memory");
}
#define CP_COMMIT() asm volatile("cp.async.commit_group;" ::: "memory")
#define CP_WAIT(N)  asm volatile("cp.async.wait_group %0;" :: "n"(N) : "memory")

// ===========================================================================
// Elementwise fp32 -> fp16 conversion pre-pass
// ===========================================================================
__global__ void cvt_f16_kernel(const float4* __restrict__ in,
                               __half2* __restrict__ out, int n4)
{
    int i = blockIdx.x * blockDim.x + threadIdx.x;
    if (i < n4) {
        float4 v = in[i];
        out[2 * i]     = __floats2half2_rn(v.x, v.y);
        out[2 * i + 1] = __floats2half2_rn(v.z, v.w);
    }
}

// ===========================================================================
// fp16 mma.sync GEMM:  C[m][n] = sum_k A[m][k]*B[n][k]   (NT, both K-major)
// m16n8k16, BM=BN=128, BK=32 halves. 4-stage cp.async ring, ldmatrix.x4.
// 128 threads (4 warps 2x2), warp tile 64x64.
// EPI=0: fp32 row-major store. EPI=1: fp16 qkv scatter to [B,H,T,d].
// ===========================================================================
#define BM 128
#define BN 128
#define BKH 32                     // k halves per tile
#define ROWB 80                    // row stride bytes (32h=64B + 16B pad) conflict-free
#define NSTG 4
#define STG_BYTES (BM*ROWB)        // 10240
#define GEMM_SMEM (2*NSTG*STG_BYTES)  // 81920

template <int EPI>
__global__ void __launch_bounds__(128, 2)
gemm_mma(const __half* __restrict__ A, const __half* __restrict__ B,
         float* __restrict__ Co, __half* __restrict__ Cq, __half* __restrict__ Ck,
         __half* __restrict__ Cv, int M, int N, int K)
{
    extern __shared__ __align__(16) char smg[];

    const int tid = threadIdx.x;
    const int lane = tid & 31;
    const int wid = tid >> 5;            // 0..3
    const int wm = (wid & 1) * 64;
    const int wn = (wid >> 1) * 64;
    const int m0 = blockIdx.y * BM;
    const int n0 = blockIdx.x * BN;

    float acc[4][8][4];
#pragma unroll
    for (int i = 0; i < 4; i++)
#pragma unroll
        for (int j = 0; j < 8; j++)
#pragma unroll
            for (int q = 0; q < 4; q++) acc[i][j][q] = 0.f;

    const int NK = K / BKH;

    const int cr = tid >> 2;             // base row (x4 via +32*i)
    const int cc = tid & 3;              // 16B (8-half) chunk within row
    const uint32_t as_sm = (uint32_t)__cvta_generic_to_shared(&smg[0]);
    const uint32_t bs_sm = as_sm + NSTG * STG_BYTES;

    // ldmatrix per-lane addresses (stage 0)
    const uint32_t a_addr = as_sm + (wm + (lane & 15)) * ROWB + ((lane >> 4) << 4);
    const uint32_t b_addr = bs_sm + (wn + ((lane >> 4) << 3) + (lane & 7)) * ROWB
                                  + (((lane >> 3) & 1) << 4);

    const __half* Agp = A + (long)(m0 + cr) * K + cc * 8;
    const __half* Bgp = B + (long)(n0 + cr) * K + cc * 8;
    const long rowK32 = (long)32 * K;

#define ISSUE_STAGE(stg, kt_) do {                                          \
        const uint32_t asx = as_sm + (stg) * STG_BYTES + cr * ROWB + cc * 16; \
        const uint32_t bsx = bs_sm + (stg) * STG_BYTES + cr * ROWB + cc * 16; \
        const __half* ag = Agp + (long)(kt_) * BKH;                         \
        const __half* bg = Bgp + (long)(kt_) * BKH;                         \
        _Pragma("unroll")                                                   \
        for (int i_ = 0; i_ < 4; i_++) {                                    \
            cp16(asx + i_ * (32 * ROWB), ag + i_ * rowK32);                 \
            cp16(bsx + i_ * (32 * ROWB), bg + i_ * rowK32);                 \
        }                                                                   \
        CP_COMMIT();                                                        \
    } while (0)

    ISSUE_STAGE(0, 0);
    ISSUE_STAGE(1, 1);
    ISSUE_STAGE(2, 2);

    for (int kt = 0; kt < NK; kt++) {
        const int s = kt & (NSTG - 1);
        CP_WAIT(NSTG - 2);
        __syncthreads();

        if (kt + NSTG - 1 < NK) {
            ISSUE_STAGE((kt + NSTG - 1) & (NSTG - 1), kt + NSTG - 1);
        } else {
            CP_COMMIT();
        }

        const uint32_t as_s = a_addr + s * STG_BYTES;
        const uint32_t bs_s = b_addr + s * STG_BYTES;
#pragma unroll
        for (int ks = 0; ks < 2; ks++) {
            const uint32_t kb = ks * 32;               // 16 halves
            uint32_t af[4][4], bf[8][2];
#pragma unroll
            for (int i = 0; i < 4; i++)
                ldsm_x4(af[i], as_s + kb + i * (16 * ROWB));
#pragma unroll
            for (int jj = 0; jj < 4; jj++)
                ldsm_x4(&bf[jj * 2][0], bs_s + kb + jj * (16 * ROWB));
#pragma unroll
            for (int i = 0; i < 4; i++)
#pragma unroll
                for (int j = 0; j < 8; j++)
                    mma_f16(acc[i][j], af[i], bf[j]);
        }
    }
#undef ISSUE_STAGE

    const int ar = lane >> 2;
    const int ac = lane & 3;

#pragma unroll
    for (int i = 0; i < 4; i++) {
        const int mrow0 = m0 + wm + i * 16 + ar;
#pragma unroll
        for (int j = 0; j < 8; j++) {
            const int n = n0 + wn + j * 8 + ac * 2;
            if (EPI == 0) {
                float* d0 = Co + (long)mrow0 * N + n;
                float* d1 = Co + (long)(mrow0 + 8) * N + n;
                *(float2*)d0 = make_float2(acc[i][j][0], acc[i][j][1]);
                *(float2*)d1 = make_float2(acc[i][j][2], acc[i][j][3]);
            } else {
                const int which = n >> 11;
                const int rem = n & 2047;
                const int h = rem >> 7, dd = rem & 127;
                __half* base = (which == 0) ? Cq : (which == 1) ? Ck : Cv;
                const int b0_ = mrow0 >> 11, t0 = mrow0 & 2047;
                const int b1_ = (mrow0 + 8) >> 11, t1 = (mrow0 + 8) & 2047;
                __half* d0 = base + (((long)(b0_ * Hp + h) * Tp + t0) * Dp + dd);
                __half* d1 = base + (((long)(b1_ * Hp + h) * Tp + t1) * Dp + dd);
                *(__half2*)d0 = __floats2half2_rn(acc[i][j][0], acc[i][j][1]);
                *(__half2*)d1 = __floats2half2_rn(acc[i][j][2], acc[i][j][3]);
            }
        }
    }
}

// ===========================================================================
// Tensor-core causal flash attention (fp16 m16n8k16, fp32 accum/softmax).
// Block: 128 queries, 8 warps (16 rows each). KV tile = 64.
// Smem (halves): Qs[128][136], Ks[64][136], Vs[64][136], Ps[8][16][72]
// ===========================================================================
#define QS_STR 136
#define KV_STR 136
#define P_STR  72
#define ATTN3_SMEM ((128*QS_STR + 64*KV_STR + 64*KV_STR + 8*16*P_STR) * 2)

__global__ void __launch_bounds__(256)
attn_tc(const __half* __restrict__ Qg, const __half* __restrict__ Kg,
        const __half* __restrict__ Vg, __half* __restrict__ Og)
{
    extern __shared__ __half sma[];
    __half* Qs = sma;                      // [128][136]
    __half* Ks = Qs + 128 * QS_STR;        // [64][136]
    __half* Vs = Ks + 64 * KV_STR;         // [64][136]
    __half* Ps = Vs + 64 * KV_STR;         // [8][16][72]

    const int tid = threadIdx.x;
    const int lane = tid & 31;
    const int w = tid >> 5;
    const int g = lane >> 2;
    const int t4 = lane & 3;
    const int qt = gridDim.x - 1 - blockIdx.x;   // heavy tiles first
    const int bh = blockIdx.y;
    const int q0 = qt * 128;
    const long base = (long)bh * Tp * Dp;
    __half* Pw = Ps + w * 16 * P_STR;

    const uint32_t qs_sm = (uint32_t)__cvta_generic_to_shared(Qs);
    const uint32_t ks_sm = (uint32_t)__cvta_generic_to_shared(Ks);
    const uint32_t vs_sm = (uint32_t)__cvta_generic_to_shared(Vs);
    const uint32_t ps_sm = (uint32_t)__cvta_generic_to_shared(Pw);

    // per-lane ldmatrix base addresses
    const uint32_t q_addr = qs_sm + (w * 16 + (lane & 15)) * (QS_STR * 2) + ((lane >> 4) << 4);
    const uint32_t k_addr = ks_sm + (((lane >> 4) << 3) + (lane & 7)) * (KV_STR * 2)
                                  + (((lane >> 3) & 1) << 4);
    const uint32_t p_addr = ps_sm + (lane & 15) * (P_STR * 2) + ((lane >> 4) << 4);
    const uint32_t v_addr = vs_sm + ((((lane >> 3) & 1) << 3) + (lane & 7)) * (KV_STR * 2)
                                  + ((lane >> 4) << 4);

    // stage Q tile (half, direct copy)
    for (int i = tid; i < 128 * 16; i += 256) {
        int r = i >> 4, c8 = i & 15;
        *(uint4*)&Qs[r * QS_STR + c8 * 8] =
            *(const uint4*)(Qg + base + (long)(q0 + r) * Dp + c8 * 8);
    }

    float oacc[16][4];
#pragma unroll
    for (int i = 0; i < 16; i++)
#pragma unroll
        for (int q = 0; q < 4; q++) oacc[i][q] = 0.f;
    float m_lo = -1e30f, m_hi = -1e30f, l_lo = 0.f, l_hi = 0.f;

    const int row_lo = q0 + w * 16 + g;
    const int row_hi = row_lo + 8;
    const int njt = qt * 2 + 2;

    for (int j = 0; j < njt; j++) {
        __syncthreads();
        for (int i = tid; i < 64 * 16; i += 256) {
            int r = i >> 4, c8 = i & 15;
            *(uint4*)&Ks[r * KV_STR + c8 * 8] =
                *(const uint4*)(Kg + base + (long)(j * 64 + r) * Dp + c8 * 8);
            *(uint4*)&Vs[r * KV_STR + c8 * 8] =
                *(const uint4*)(Vg + base + (long)(j * 64 + r) * Dp + c8 * 8);
        }
        __syncthreads();

        // ---- S = Q K^T (16 x 64), fp16 mma ----
        float sf[8][4];
#pragma unroll
        for (int n = 0; n < 8; n++)
#pragma unroll
            for (int q = 0; q < 4; q++) sf[n][q] = 0.f;

#pragma unroll
        for (int kc = 0; kc < 8; kc++) {
            uint32_t af[4], bf[8][2];
            ldsm_x4(af, q_addr + kc * 32);
#pragma unroll
            for (int jj = 0; jj < 4; jj++)
                ldsm_x4(&bf[jj * 2][0], k_addr + jj * (16 * KV_STR * 2) + kc * 32);
#pragma unroll
            for (int n = 0; n < 8; n++)
                mma_f16(sf[n], af, bf[n]);
        }

        // ---- mask + scale ----
        if (j * 64 + 63 <= q0 + w * 16) {
#pragma unroll
            for (int n = 0; n < 8; n++)
#pragma unroll
                for (int q = 0; q < 4; q++) sf[n][q] *= SCALE;
        } else {
#pragma unroll
            for (int n = 0; n < 8; n++) {
                const int col = j * 64 + n * 8 + 2 * t4;
                sf[n][0] = (col     <= row_lo) ? sf[n][0] * SCALE : -1e30f;
                sf[n][1] = (col + 1 <= row_lo) ? sf[n][1] * SCALE : -1e30f;
                sf[n][2] = (col     <= row_hi) ? sf[n][2] * SCALE : -1e30f;
                sf[n][3] = (col + 1 <= row_hi) ? sf[n][3] * SCALE : -1e30f;
            }
        }

        // ---- online softmax (fp32) ----
        float tl = -1e30f, th = -1e30f;
#pragma unroll
        for (int n = 0; n < 8; n++) {
            tl = fmaxf(tl, fmaxf(sf[n][0], sf[n][1]));
            th = fmaxf(th, fmaxf(sf[n][2], sf[n][3]));
        }
        tl = fmaxf(tl, __shfl_xor_sync(0xffffffffu, tl, 1));
        tl = fmaxf(tl, __shfl_xor_sync(0xffffffffu, tl, 2));
        th = fmaxf(th, __shfl_xor_sync(0xffffffffu, th, 1));
        th = fmaxf(th, __shfl_xor_sync(0xffffffffu, th, 2));
        const float mn_lo = fmaxf(m_lo, tl);
        const float mn_hi = fmaxf(m_hi, th);
        const float corr_lo = __expf(m_lo - mn_lo);
        const float corr_hi = __expf(m_hi - mn_hi);
        m_lo = mn_lo; m_hi = mn_hi;

        float sum_lo = 0.f, sum_hi = 0.f;
#pragma unroll
        for (int n = 0; n < 8; n++) {
            float p0 = __expf(sf[n][0] - m_lo);
            float p1 = __expf(sf[n][1] - m_lo);
            float p2 = __expf(sf[n][2] - m_hi);
            float p3 = __expf(sf[n][3] - m_hi);
            sum_lo += p0 + p1;
            sum_hi += p2 + p3;
            const int pc = n * 8 + 2 * t4;
            *(__half2*)&Pw[g * P_STR + pc]       = __floats2half2_rn(p0, p1);
            *(__half2*)&Pw[(g + 8) * P_STR + pc] = __floats2half2_rn(p2, p3);
        }
        sum_lo += __shfl_xor_sync(0xffffffffu, sum_lo, 1);
        sum_lo += __shfl_xor_sync(0xffffffffu, sum_lo, 2);
        sum_hi += __shfl_xor_sync(0xffffffffu, sum_hi, 1);
        sum_hi += __shfl_xor_sync(0xffffffffu, sum_hi, 2);
        l_lo = l_lo * corr_lo + sum_lo;
        l_hi = l_hi * corr_hi + sum_hi;
#pragma unroll
        for (int dt = 0; dt < 16; dt++) {
            oacc[dt][0] *= corr_lo; oacc[dt][1] *= corr_lo;
            oacc[dt][2] *= corr_hi; oacc[dt][3] *= corr_hi;
        }
        __syncwarp();

        // ---- O += P V (fp16 mma, V via ldmatrix.trans) ----
#pragma unroll
        for (int kc = 0; kc < 4; kc++) {
            uint32_t paf[4], vbf[16][2];
            ldsm_x4(paf, p_addr + kc * 32);
#pragma unroll
            for (int jj = 0; jj < 8; jj++)
                ldsm_x4_t(&vbf[jj * 2][0],
                          v_addr + kc * (16 * KV_STR * 2) + jj * 32);
#pragma unroll
            for (int dt = 0; dt < 16; dt++)
                mma_f16(oacc[dt], paf, vbf[dt]);
        }
    }

    // ---- epilogue: fp16 output for the proj GEMM ----
    const float il_lo = 1.f / l_lo;
    const float il_hi = 1.f / l_hi;
    const int b = bh >> 4, h = bh & 15;
    __half* o_lo = Og + ((long)(b * Tp + row_lo)) * Cp + h * Dp;
    __half* o_hi = Og + ((long)(b * Tp + row_hi)) * Cp + h * Dp;
#pragma unroll
    for (int dt = 0; dt < 16; dt++) {
        const int col = dt * 8 + 2 * t4;
        *(__half2*)(o_lo + col) = __floats2half2_rn(oacc[dt][0] * il_lo, oacc[dt][1] * il_lo);
        *(__half2*)(o_hi + col) = __floats2half2_rn(oacc[dt][2] * il_hi, oacc[dt][3] * il_hi);
    }
}

// ---------------------------------------------------------------------------
extern "C" void kernel_launch(void* const* d_in, const int* in_sizes, int n_in,
                              void* d_out, int out_size)
{
    const float* x      = (const float*)d_in[0];  // [B,T,C]
    const float* W_attn = (const float*)d_in[1];  // [3C,C]
    const float* W_proj = (const float*)d_in[2];  // [C,C]
    float* out = (float*)d_out;                   // [B,T,C]

    __half *pq, *pk, *pv, *pao, *pxh, *pwa, *pwp;
    cudaGetSymbolAddress((void**)&pq,  g_qh);
    cudaGetSymbolAddress((void**)&pk,  g_kh);
    cudaGetSymbolAddress((void**)&pv,  g_vh);
    cudaGetSymbolAddress((void**)&pao, g_aoh);
    cudaGetSymbolAddress((void**)&pxh, g_xh);
    cudaGetSymbolAddress((void**)&pwa, g_wah);
    cudaGetSymbolAddress((void**)&pwp, g_wph);

    cudaFuncSetAttribute(attn_tc,
                         cudaFuncAttributeMaxDynamicSharedMemorySize, ATTN3_SMEM);
    cudaFuncSetAttribute(gemm_mma<0>,
                         cudaFuncAttributeMaxDynamicSharedMemorySize, GEMM_SMEM);
    cudaFuncSetAttribute(gemm_mma<1>,
                         cudaFuncAttributeMaxDynamicSharedMemorySize, GEMM_SMEM);

    // 0) fp16 conversion pre-pass
    {
        int n4x = BTp * Cp / 4, n4a = 3 * Cp * Cp / 4, n4p = Cp * Cp / 4;
        cvt_f16_kernel<<<(n4x + 255) / 256, 256>>>((const float4*)x,      (__half2*)pxh, n4x);
        cvt_f16_kernel<<<(n4a + 255) / 256, 256>>>((const float4*)W_attn, (__half2*)pwa, n4a);
        cvt_f16_kernel<<<(n4p + 255) / 256, 256>>>((const float4*)W_proj, (__half2*)pwp, n4p);
    }
    // 1) QKV projection with fp16 scatter into [B,H,T,d]
    {
        dim3 grid(3 * Cp / BN, BTp / BM);
        gemm_mma<1><<<grid, 128, GEMM_SMEM>>>(pxh, pwa, nullptr, pq, pk, pv,
                                              BTp, 3 * Cp, Cp);
    }
    // 2) fp16 tensor-core causal flash attention -> g_aoh [B,T,C]
    {
        dim3 grid(Tp / 128, BHp);
        attn_tc<<<grid, 256, ATTN3_SMEM>>>(pq, pk, pv, pao);
    }
    // 3) output projection (fp32 output)
    {
        dim3 grid(Cp / BN, BTp / BM);
        gemm_mma<0><<<grid, 128, GEMM_SMEM>>>(pao, pwp, out, nullptr, nullptr, nullptr,
                                              BTp, Cp, Cp);
    }
}

// round 15
// speedup vs baseline: 2.2122x; 1.0969x over previous
#include <cuda_runtime.h>
#include <cuda_fp16.h>
#include <cstdint>
#include <math.h>

// Problem shape (fixed)
#define Bp 4
#define Tp 2048
#define Cp 2048
#define Hp 16
#define Dp 128
#define BHp (Bp*Hp)        // 64
#define BTp (Bp*Tp)        // 8192
#define SCALE 0.08838834764831845f  // 1/sqrt(128)

// Scratch (device globals; allocation-free per harness rules)
__device__ __half g_qh [BHp * Tp * Dp];   // [B,H,T,d]
__device__ __half g_kh [BHp * Tp * Dp];
__device__ __half g_vh [BHp * Tp * Dp];
__device__ __half g_aoh[BTp * Cp];        // attention out, [B,T,C]
__device__ __half g_xh [BTp * Cp];        // x, fp16
__device__ __half g_wah[3 * Cp * Cp];     // W_attn, fp16
__device__ __half g_wph[Cp * Cp];         // W_proj, fp16

__device__ __forceinline__ void mma_f16(float* d, const uint32_t* a, const uint32_t* b) {
    asm volatile(
        "mma.sync.aligned.m16n8k16.row.col.f32.f16.f16.f32 "
        "{%0,%1,%2,%3}, {%4,%5,%6,%7}, {%8,%9}, {%0,%1,%2,%3};"
        : "+f"(d[0]), "+f"(d[1]), "+f"(d[2]), "+f"(d[3])
        : "r"(a[0]), "r"(a[1]), "r"(a[2]), "r"(a[3]), "r"(b[0]), "r"(b[1]));
}

__device__ __forceinline__ void ldsm_x4(uint32_t* r, uint32_t addr) {
    asm volatile("ldmatrix.sync.aligned.m8n8.x4.shared.b16 {%0,%1,%2,%3}, [%4];"
                 : "=r"(r[0]), "=r"(r[1]), "=r"(r[2]), "=r"(r[3]) : "r"(addr));
}
__device__ __forceinline__ void ldsm_x4_t(uint32_t* r, uint32_t addr) {
    asm volatile("ldmatrix.sync.aligned.m8n8.x4.trans.shared.b16 {%0,%1,%2,%3}, [%4];"
                 : "=r"(r[0]), "=r"(r[1]), "=r"(r[2]), "=r"(r[3]) : "r"(addr));
}

__device__ __forceinline__ void cp16(uint32_t saddr, const void* gaddr) {
    asm volatile("cp.async.cg.shared.global [%0], [%1], 16;"
                 :: "r"(saddr), "l"(gaddr) : "memory");
}
#define CP_COMMIT() asm volatile("cp.async.commit_group;" ::: "memory")
#define CP_WAIT(N)  asm volatile("cp.async.wait_group %0;" :: "n"(N) : "memory")

// ===========================================================================
// Elementwise fp32 -> fp16 conversion pre-pass
// ===========================================================================
__global__ void cvt_f16_kernel(const float4* __restrict__ in,
                               __half2* __restrict__ out, int n4)
{
    int i = blockIdx.x * blockDim.x + threadIdx.x;
    if (i < n4) {
        float4 v = in[i];
        out[2 * i]     = __floats2half2_rn(v.x, v.y);
        out[2 * i + 1] = __floats2half2_rn(v.z, v.w);
    }
}

// ===========================================================================
// fp16 mma.sync GEMM:  C[m][n] = sum_k A[m][k]*B[n][k]   (NT, both K-major)
// m16n8k16, BM=BN=128, BK=32 halves. 4-stage cp.async ring, ldmatrix.x4.
// 256 threads (8 warps, 2x4), warp tile 64x32, 2 CTAs/SM.
// EPI=0: fp32 row-major store. EPI=1: fp16 qkv scatter to [B,H,T,d].
// ===========================================================================
#define BM 128
#define BN 128
#define BKH 32                     // k halves per tile
#define ROWB 80                    // row stride bytes, LDSM conflict-free
#define NSTG 4
#define STG_BYTES (BM*ROWB)        // 10240
#define GEMM_SMEM (2*NSTG*STG_BYTES)  // 81920

template <int EPI>
__global__ void __launch_bounds__(256, 2)
gemm_mma(const __half* __restrict__ A, const __half* __restrict__ B,
         float* __restrict__ Co, __half* __restrict__ Cq, __half* __restrict__ Ck,
         __half* __restrict__ Cv, int M, int N, int K)
{
    extern __shared__ __align__(16) char smg[];

    const int tid = threadIdx.x;
    const int lane = tid & 31;
    const int wid = tid >> 5;            // 0..7
    const int wm = (wid & 1) * 64;
    const int wn = (wid >> 1) * 32;
    const int m0 = blockIdx.y * BM;
    const int n0 = blockIdx.x * BN;

    float acc[4][4][4];
#pragma unroll
    for (int i = 0; i < 4; i++)
#pragma unroll
        for (int j = 0; j < 4; j++)
#pragma unroll
            for (int q = 0; q < 4; q++) acc[i][j][q] = 0.f;

    const int NK = K / BKH;

    const int cr = tid >> 2;             // base row 0..63 (x2 via +64*i)
    const int cc = tid & 3;              // 16B (8-half) chunk within row
    const uint32_t as_sm = (uint32_t)__cvta_generic_to_shared(&smg[0]);
    const uint32_t bs_sm = as_sm + NSTG * STG_BYTES;

    // ldmatrix per-lane addresses (stage 0)
    const uint32_t a_addr = as_sm + (wm + (lane & 15)) * ROWB + ((lane >> 4) << 4);
    const uint32_t b_addr = bs_sm + (wn + ((lane >> 4) << 3) + (lane & 7)) * ROWB
                                  + (((lane >> 3) & 1) << 4);

    const __half* Agp = A + (long)(m0 + cr) * K + cc * 8;
    const __half* Bgp = B + (long)(n0 + cr) * K + cc * 8;
    const long rowK64 = (long)64 * K;

#define ISSUE_STAGE(stg, kt_) do {                                          \
        const uint32_t asx = as_sm + (stg) * STG_BYTES + cr * ROWB + cc * 16; \
        const uint32_t bsx = bs_sm + (stg) * STG_BYTES + cr * ROWB + cc * 16; \
        const __half* ag = Agp + (long)(kt_) * BKH;                         \
        const __half* bg = Bgp + (long)(kt_) * BKH;                         \
        _Pragma("unroll")                                                   \
        for (int i_ = 0; i_ < 2; i_++) {                                    \
            cp16(asx + i_ * (64 * ROWB), ag + i_ * rowK64);                 \
            cp16(bsx + i_ * (64 * ROWB), bg + i_ * rowK64);                 \
        }                                                                   \
        CP_COMMIT();                                                        \
    } while (0)

    ISSUE_STAGE(0, 0);
    ISSUE_STAGE(1, 1);
    ISSUE_STAGE(2, 2);

    for (int kt = 0; kt < NK; kt++) {
        const int s = kt & (NSTG - 1);
        CP_WAIT(NSTG - 2);
        __syncthreads();

        if (kt + NSTG - 1 < NK) {
            ISSUE_STAGE((kt + NSTG - 1) & (NSTG - 1), kt + NSTG - 1);
        } else {
            CP_COMMIT();
        }

        const uint32_t as_s = a_addr + s * STG_BYTES;
        const uint32_t bs_s = b_addr + s * STG_BYTES;
#pragma unroll
        for (int ks = 0; ks < 2; ks++) {
            const uint32_t kb = ks * 32;               // 16 halves
            uint32_t af[4][4], bf[4][2];
#pragma unroll
            for (int i = 0; i < 4; i++)
                ldsm_x4(af[i], as_s + kb + i * (16 * ROWB));
#pragma unroll
            for (int jj = 0; jj < 2; jj++)
                ldsm_x4(&bf[jj * 2][0], bs_s + kb + jj * (16 * ROWB));
#pragma unroll
            for (int i = 0; i < 4; i++)
#pragma unroll
                for (int j = 0; j < 4; j++)
                    mma_f16(acc[i][j], af[i], bf[j]);
        }
    }
#undef ISSUE_STAGE

    const int ar = lane >> 2;
    const int ac = lane & 3;

#pragma unroll
    for (int i = 0; i < 4; i++) {
        const int mrow0 = m0 + wm + i * 16 + ar;
#pragma unroll
        for (int j = 0; j < 4; j++) {
            const int n = n0 + wn + j * 8 + ac * 2;
            if (EPI == 0) {
                float* d0 = Co + (long)mrow0 * N + n;
                float* d1 = Co + (long)(mrow0 + 8) * N + n;
                *(float2*)d0 = make_float2(acc[i][j][0], acc[i][j][1]);
                *(float2*)d1 = make_float2(acc[i][j][2], acc[i][j][3]);
            } else {
                const int which = n >> 11;
                const int rem = n & 2047;
                const int h = rem >> 7, dd = rem & 127;
                __half* base = (which == 0) ? Cq : (which == 1) ? Ck : Cv;
                const int b0_ = mrow0 >> 11, t0 = mrow0 & 2047;
                const int b1_ = (mrow0 + 8) >> 11, t1 = (mrow0 + 8) & 2047;
                __half* d0 = base + (((long)(b0_ * Hp + h) * Tp + t0) * Dp + dd);
                __half* d1 = base + (((long)(b1_ * Hp + h) * Tp + t1) * Dp + dd);
                *(__half2*)d0 = __floats2half2_rn(acc[i][j][0], acc[i][j][1]);
                *(__half2*)d1 = __floats2half2_rn(acc[i][j][2], acc[i][j][3]);
            }
        }
    }
}

// ===========================================================================
// Tensor-core causal flash attention (fp16 m16n8k16, fp32 accum/softmax).
// Block: 128 queries, 8 warps (16 rows each). KV tile = 64, 2-stage cp.async.
// ===========================================================================
#define QS_STR 136
#define KV_STR 136
#define P_STR  72
#define KVSTG_BYTES (64*KV_STR*2)   // 17408
#define ATTN4_SMEM ((128*QS_STR + 2*64*KV_STR + 2*64*KV_STR + 8*16*P_STR) * 2)

__global__ void __launch_bounds__(256)
attn_tc(const __half* __restrict__ Qg, const __half* __restrict__ Kg,
        const __half* __restrict__ Vg, __half* __restrict__ Og)
{
    extern __shared__ __half sma[];
    __half* Qs = sma;                          // [128][136]
    __half* Ps = Qs + 128 * QS_STR + 4 * 64 * KV_STR;  // [8][16][72]

    const int tid = threadIdx.x;
    const int lane = tid & 31;
    const int w = tid >> 5;
    const int g = lane >> 2;
    const int t4 = lane & 3;
    const int qt = gridDim.x - 1 - blockIdx.x;   // heavy tiles first
    const int bh = blockIdx.y;
    const int q0 = qt * 128;
    const long base = (long)bh * Tp * Dp;
    __half* Pw = Ps + w * 16 * P_STR;

    const uint32_t qs_sm = (uint32_t)__cvta_generic_to_shared(Qs);
    const uint32_t ks_sm = qs_sm + 128 * QS_STR * 2;
    const uint32_t vs_sm = ks_sm + 2 * KVSTG_BYTES;
    const uint32_t ps_sm = (uint32_t)__cvta_generic_to_shared(Pw);

    // per-lane ldmatrix base addresses (stage 0)
    const uint32_t q_addr = qs_sm + (w * 16 + (lane & 15)) * (QS_STR * 2) + ((lane >> 4) << 4);
    const uint32_t k_addr = ks_sm + (((lane >> 4) << 3) + (lane & 7)) * (KV_STR * 2)
                                  + (((lane >> 3) & 1) << 4);
    const uint32_t p_addr = ps_sm + (lane & 15) * (P_STR * 2) + ((lane >> 4) << 4);
    const uint32_t v_addr = vs_sm + ((((lane >> 3) & 1) << 3) + (lane & 7)) * (KV_STR * 2)
                                  + ((lane >> 4) << 4);

    // KV tile cp.async: 8 chunks of 16B per thread (4 K + 4 V)
    const int kvr = tid >> 4;      // base row 0..15 (x4 via +16*i)
    const int kvc = tid & 15;      // 16B chunk in row

    // NOTE: gmem row offset includes kvr (bug fixed from R14).
#define ISSUE_KV(st, jj) do {                                                \
        const __half* kg = Kg + base + (long)((jj) * 64 + kvr) * Dp + kvc * 8; \
        const __half* vg = Vg + base + (long)((jj) * 64 + kvr) * Dp + kvc * 8; \
        const uint32_t kx = ks_sm + (st) * KVSTG_BYTES + kvr * (KV_STR * 2) + kvc * 16; \
        const uint32_t vx = vs_sm + (st) * KVSTG_BYTES + kvr * (KV_STR * 2) + kvc * 16; \
        _Pragma("unroll")                                                    \
        for (int i_ = 0; i_ < 4; i_++) {                                     \
            cp16(kx + i_ * (16 * KV_STR * 2), kg + (long)(i_ * 16) * Dp);    \
            cp16(vx + i_ * (16 * KV_STR * 2), vg + (long)(i_ * 16) * Dp);    \
        }                                                                    \
        CP_COMMIT();                                                         \
    } while (0)

    // stage Q tile (half, direct copy)
    for (int i = tid; i < 128 * 16; i += 256) {
        int r = i >> 4, c8 = i & 15;
        *(uint4*)&Qs[r * QS_STR + c8 * 8] =
            *(const uint4*)(Qg + base + (long)(q0 + r) * Dp + c8 * 8);
    }

    float oacc[16][4];
#pragma unroll
    for (int i = 0; i < 16; i++)
#pragma unroll
        for (int q = 0; q < 4; q++) oacc[i][q] = 0.f;
    float m_lo = -1e30f, m_hi = -1e30f, l_lo = 0.f, l_hi = 0.f;

    const int row_lo = q0 + w * 16 + g;
    const int row_hi = row_lo + 8;
    const int njt = qt * 2 + 2;

    ISSUE_KV(0, 0);

    for (int j = 0; j < njt; j++) {
        const int s = j & 1;
        if (j + 1 < njt) {
            ISSUE_KV(s ^ 1, j + 1);
            CP_WAIT(1);
        } else {
            CP_WAIT(0);
        }
        __syncthreads();

        const uint32_t k_s = k_addr + s * KVSTG_BYTES;
        const uint32_t v_s = v_addr + s * KVSTG_BYTES;

        // ---- S = Q K^T (16 x 64), fp16 mma ----
        float sf[8][4];
#pragma unroll
        for (int n = 0; n < 8; n++)
#pragma unroll
            for (int q = 0; q < 4; q++) sf[n][q] = 0.f;

#pragma unroll
        for (int kc = 0; kc < 8; kc++) {
            uint32_t af[4], bf[8][2];
            ldsm_x4(af, q_addr + kc * 32);
#pragma unroll
            for (int jj = 0; jj < 4; jj++)
                ldsm_x4(&bf[jj * 2][0], k_s + jj * (16 * KV_STR * 2) + kc * 32);
#pragma unroll
            for (int n = 0; n < 8; n++)
                mma_f16(sf[n], af, bf[n]);
        }

        // ---- mask + scale ----
        if (j * 64 + 63 <= q0 + w * 16) {
#pragma unroll
            for (int n = 0; n < 8; n++)
#pragma unroll
                for (int q = 0; q < 4; q++) sf[n][q] *= SCALE;
        } else {
#pragma unroll
            for (int n = 0; n < 8; n++) {
                const int col = j * 64 + n * 8 + 2 * t4;
                sf[n][0] = (col     <= row_lo) ? sf[n][0] * SCALE : -1e30f;
                sf[n][1] = (col + 1 <= row_lo) ? sf[n][1] * SCALE : -1e30f;
                sf[n][2] = (col     <= row_hi) ? sf[n][2] * SCALE : -1e30f;
                sf[n][3] = (col + 1 <= row_hi) ? sf[n][3] * SCALE : -1e30f;
            }
        }

        // ---- online softmax (fp32 exp, as in R13) ----
        float tl = -1e30f, th = -1e30f;
#pragma unroll
        for (int n = 0; n < 8; n++) {
            tl = fmaxf(tl, fmaxf(sf[n][0], sf[n][1]));
            th = fmaxf(th, fmaxf(sf[n][2], sf[n][3]));
        }
        tl = fmaxf(tl, __shfl_xor_sync(0xffffffffu, tl, 1));
        tl = fmaxf(tl, __shfl_xor_sync(0xffffffffu, tl, 2));
        th = fmaxf(th, __shfl_xor_sync(0xffffffffu, th, 1));
        th = fmaxf(th, __shfl_xor_sync(0xffffffffu, th, 2));
        const float mn_lo = fmaxf(m_lo, tl);
        const float mn_hi = fmaxf(m_hi, th);
        const float corr_lo = __expf(m_lo - mn_lo);
        const float corr_hi = __expf(m_hi - mn_hi);
        m_lo = mn_lo; m_hi = mn_hi;

        float sum_lo = 0.f, sum_hi = 0.f;
#pragma unroll
        for (int n = 0; n < 8; n++) {
            float p0 = __expf(sf[n][0] - m_lo);
            float p1 = __expf(sf[n][1] - m_lo);
            float p2 = __expf(sf[n][2] - m_hi);
            float p3 = __expf(sf[n][3] - m_hi);
            sum_lo += p0 + p1;
            sum_hi += p2 + p3;
            const int pc = n * 8 + 2 * t4;
            *(__half2*)&Pw[g * P_STR + pc]       = __floats2half2_rn(p0, p1);
            *(__half2*)&Pw[(g + 8) * P_STR + pc] = __floats2half2_rn(p2, p3);
        }
        sum_lo += __shfl_xor_sync(0xffffffffu, sum_lo, 1);
        sum_lo += __shfl_xor_sync(0xffffffffu, sum_lo, 2);
        sum_hi += __shfl_xor_sync(0xffffffffu, sum_hi, 1);
        sum_hi += __shfl_xor_sync(0xffffffffu, sum_hi, 2);
        l_lo = l_lo * corr_lo + sum_lo;
        l_hi = l_hi * corr_hi + sum_hi;
#pragma unroll
        for (int dt = 0; dt < 16; dt++) {
            oacc[dt][0] *= corr_lo; oacc[dt][1] *= corr_lo;
            oacc[dt][2] *= corr_hi; oacc[dt][3] *= corr_hi;
        }
        __syncwarp();

        // ---- O += P V (fp16 mma, V via ldmatrix.trans) ----
#pragma unroll
        for (int kc = 0; kc < 4; kc++) {
            uint32_t paf[4], vbf[16][2];
            ldsm_x4(paf, p_addr + kc * 32);
#pragma unroll
            for (int jj = 0; jj < 8; jj++)
                ldsm_x4_t(&vbf[jj * 2][0],
                          v_s + kc * (16 * KV_STR * 2) + jj * 32);
#pragma unroll
            for (int dt = 0; dt < 16; dt++)
                mma_f16(oacc[dt], paf, vbf[dt]);
        }
        __syncthreads();
    }

    // ---- epilogue: fp16 output for the proj GEMM ----
    const float il_lo = 1.f / l_lo;
    const float il_hi = 1.f / l_hi;
    const int b = bh >> 4, h = bh & 15;
    __half* o_lo = Og + ((long)(b * Tp + row_lo)) * Cp + h * Dp;
    __half* o_hi = Og + ((long)(b * Tp + row_hi)) * Cp + h * Dp;
#pragma unroll
    for (int dt = 0; dt < 16; dt++) {
        const int col = dt * 8 + 2 * t4;
        *(__half2*)(o_lo + col) = __floats2half2_rn(oacc[dt][0] * il_lo, oacc[dt][1] * il_lo);
        *(__half2*)(o_hi + col) = __floats2half2_rn(oacc[dt][2] * il_hi, oacc[dt][3] * il_hi);
    }
}

// ---------------------------------------------------------------------------
extern "C" void kernel_launch(void* const* d_in, const int* in_sizes, int n_in,
                              void* d_out, int out_size)
{
    const float* x      = (const float*)d_in[0];  // [B,T,C]
    const float* W_attn = (const float*)d_in[1];  // [3C,C]
    const float* W_proj = (const float*)d_in[2];  // [C,C]
    float* out = (float*)d_out;                   // [B,T,C]

    __half *pq, *pk, *pv, *pao, *pxh, *pwa, *pwp;
    cudaGetSymbolAddress((void**)&pq,  g_qh);
    cudaGetSymbolAddress((void**)&pk,  g_kh);
    cudaGetSymbolAddress((void**)&pv,  g_vh);
    cudaGetSymbolAddress((void**)&pao, g_aoh);
    cudaGetSymbolAddress((void**)&pxh, g_xh);
    cudaGetSymbolAddress((void**)&pwa, g_wah);
    cudaGetSymbolAddress((void**)&pwp, g_wph);

    cudaFuncSetAttribute(attn_tc,
                         cudaFuncAttributeMaxDynamicSharedMemorySize, ATTN4_SMEM);
    cudaFuncSetAttribute(gemm_mma<0>,
                         cudaFuncAttributeMaxDynamicSharedMemorySize, GEMM_SMEM);
    cudaFuncSetAttribute(gemm_mma<1>,
                         cudaFuncAttributeMaxDynamicSharedMemorySize, GEMM_SMEM);

    // 0) fp16 conversion pre-pass
    {
        int n4x = BTp * Cp / 4, n4a = 3 * Cp * Cp / 4, n4p = Cp * Cp / 4;
        cvt_f16_kernel<<<(n4x + 255) / 256, 256>>>((const float4*)x,      (__half2*)pxh, n4x);
        cvt_f16_kernel<<<(n4a + 255) / 256, 256>>>((const float4*)W_attn, (__half2*)pwa, n4a);
        cvt_f16_kernel<<<(n4p + 255) / 256, 256>>>((const float4*)W_proj, (__half2*)pwp, n4p);
    }
    // 1) QKV projection with fp16 scatter into [B,H,T,d]
    {
        dim3 grid(3 * Cp / BN, BTp / BM);
        gemm_mma<1><<<grid, 256, GEMM_SMEM>>>(pxh, pwa, nullptr, pq, pk, pv,
                                              BTp, 3 * Cp, Cp);
    }
    // 2) fp16 tensor-core causal flash attention -> g_aoh [B,T,C]
    {
        dim3 grid(Tp / 128, BHp);
        attn_tc<<<grid, 256, ATTN4_SMEM>>>(pq, pk, pv, pao);
    }
    // 3) output projection (fp32 output)
    {
        dim3 grid(Cp / BN, BTp / BM);
        gemm_mma<0><<<grid, 256, GEMM_SMEM>>>(pao, pwp, out, nullptr, nullptr, nullptr,
                                              BTp, Cp, Cp);
    }
}

// round 17
// speedup vs baseline: 2.3642x; 1.0687x over previous
#include <cuda_runtime.h>
#include <cuda_fp16.h>
#include <cstdint>
#include <math.h>

// Problem shape (fixed)
#define Bp 4
#define Tp 2048
#define Cp 2048
#define Hp 16
#define Dp 128
#define BHp (Bp*Hp)        // 64
#define BTp (Bp*Tp)        // 8192
#define SCALE 0.08838834764831845f  // 1/sqrt(128)

// Scratch (device globals; allocation-free per harness rules)
__device__ __half g_qh [BHp * Tp * Dp];   // [B,H,T,d]
__device__ __half g_kh [BHp * Tp * Dp];
__device__ __half g_vh [BHp * Tp * Dp];
__device__ __half g_aoh[BTp * Cp];        // attention out, [B,T,C]
__device__ __half g_xh [BTp * Cp];        // x, fp16
__device__ __half g_wah[3 * Cp * Cp];     // W_attn, fp16
__device__ __half g_wph[Cp * Cp];         // W_proj, fp16

__device__ __forceinline__ void mma_f16(float* d, const uint32_t* a, const uint32_t* b) {
    asm volatile(
        "mma.sync.aligned.m16n8k16.row.col.f32.f16.f16.f32 "
        "{%0,%1,%2,%3}, {%4,%5,%6,%7}, {%8,%9}, {%0,%1,%2,%3};"
        : "+f"(d[0]), "+f"(d[1]), "+f"(d[2]), "+f"(d[3])
        : "r"(a[0]), "r"(a[1]), "r"(a[2]), "r"(a[3]), "r"(b[0]), "r"(b[1]));
}

__device__ __forceinline__ void ldsm_x4(uint32_t* r, uint32_t addr) {
    asm volatile("ldmatrix.sync.aligned.m8n8.x4.shared.b16 {%0,%1,%2,%3}, [%4];"
                 : "=r"(r[0]), "=r"(r[1]), "=r"(r[2]), "=r"(r[3]) : "r"(addr));
}
__device__ __forceinline__ void ldsm_x4_t(uint32_t* r, uint32_t addr) {
    asm volatile("ldmatrix.sync.aligned.m8n8.x4.trans.shared.b16 {%0,%1,%2,%3}, [%4];"
                 : "=r"(r[0]), "=r"(r[1]), "=r"(r[2]), "=r"(r[3]) : "r"(addr));
}

__device__ __forceinline__ void cp16(uint32_t saddr, const void* gaddr) {
    asm volatile("cp.async.cg.shared.global [%0], [%1], 16;"
                 :: "r"(saddr), "l"(gaddr) : "memory");
}
#define CP_COMMIT() asm volatile("cp.async.commit_group;" ::: "memory")
#define CP_WAIT(N)  asm volatile("cp.async.wait_group %0;" :: "n"(N) : "memory")

// ===========================================================================
// Elementwise fp32 -> fp16 conversion pre-pass
// ===========================================================================
__global__ void cvt_f16_kernel(const float4* __restrict__ in,
                               __half2* __restrict__ out, int n4)
{
    int i = blockIdx.x * blockDim.x + threadIdx.x;
    if (i < n4) {
        float4 v = in[i];
        out[2 * i]     = __floats2half2_rn(v.x, v.y);
        out[2 * i + 1] = __floats2half2_rn(v.z, v.w);
    }
}

// ===========================================================================
// fp16 mma.sync GEMM (R13 config — best measured):
// C[m][n] = sum_k A[m][k]*B[n][k]   (NT, both K-major)
// m16n8k16, BM=BN=128, BK=32 halves. 4-stage cp.async ring, ldmatrix.x4.
// 128 threads (4 warps, 2x2), warp tile 64x64, 2 CTAs/SM.
// EPI=0: fp32 row-major store. EPI=1: fp16 qkv scatter to [B,H,T,d].
// ===========================================================================
#define BM 128
#define BN 128
#define BKH 32                     // k halves per tile
#define ROWB 80                    // row stride bytes, LDSM conflict-free
#define NSTG 4
#define STG_BYTES (BM*ROWB)        // 10240
#define GEMM_SMEM (2*NSTG*STG_BYTES)  // 81920

template <int EPI>
__global__ void __launch_bounds__(128, 2)
gemm_mma(const __half* __restrict__ A, const __half* __restrict__ B,
         float* __restrict__ Co, __half* __restrict__ Cq, __half* __restrict__ Ck,
         __half* __restrict__ Cv, int M, int N, int K)
{
    extern __shared__ __align__(16) char smg[];

    const int tid = threadIdx.x;
    const int lane = tid & 31;
    const int wid = tid >> 5;            // 0..3
    const int wm = (wid & 1) * 64;
    const int wn = (wid >> 1) * 64;
    const int m0 = blockIdx.y * BM;
    const int n0 = blockIdx.x * BN;

    float acc[4][8][4];
#pragma unroll
    for (int i = 0; i < 4; i++)
#pragma unroll
        for (int j = 0; j < 8; j++)
#pragma unroll
            for (int q = 0; q < 4; q++) acc[i][j][q] = 0.f;

    const int NK = K / BKH;

    const int cr = tid >> 2;             // base row 0..31 (x4 via +32*i)
    const int cc = tid & 3;              // 16B (8-half) chunk within row
    const uint32_t as_sm = (uint32_t)__cvta_generic_to_shared(&smg[0]);
    const uint32_t bs_sm = as_sm + NSTG * STG_BYTES;

    // ldmatrix per-lane addresses (stage 0)
    const uint32_t a_addr = as_sm + (wm + (lane & 15)) * ROWB + ((lane >> 4) << 4);
    const uint32_t b_addr = bs_sm + (wn + ((lane >> 4) << 3) + (lane & 7)) * ROWB
                                  + (((lane >> 3) & 1) << 4);

    const __half* Agp = A + (long)(m0 + cr) * K + cc * 8;
    const __half* Bgp = B + (long)(n0 + cr) * K + cc * 8;
    const long rowK32 = (long)32 * K;

#define ISSUE_STAGE(stg, kt_) do {                                          \
        const uint32_t asx = as_sm + (stg) * STG_BYTES + cr * ROWB + cc * 16; \
        const uint32_t bsx = bs_sm + (stg) * STG_BYTES + cr * ROWB + cc * 16; \
        const __half* ag = Agp + (long)(kt_) * BKH;                         \
        const __half* bg = Bgp + (long)(kt_) * BKH;                         \
        _Pragma("unroll")                                                   \
        for (int i_ = 0; i_ < 4; i_++) {                                    \
            cp16(asx + i_ * (32 * ROWB), ag + i_ * rowK32);                 \
            cp16(bsx + i_ * (32 * ROWB), bg + i_ * rowK32);                 \
        }                                                                   \
        CP_COMMIT();                                                        \
    } while (0)

    ISSUE_STAGE(0, 0);
    ISSUE_STAGE(1, 1);
    ISSUE_STAGE(2, 2);

    for (int kt = 0; kt < NK; kt++) {
        const int s = kt & (NSTG - 1);
        CP_WAIT(NSTG - 2);
        __syncthreads();

        if (kt + NSTG - 1 < NK) {
            ISSUE_STAGE((kt + NSTG - 1) & (NSTG - 1), kt + NSTG - 1);
        } else {
            CP_COMMIT();
        }

        const uint32_t as_s = a_addr + s * STG_BYTES;
        const uint32_t bs_s = b_addr + s * STG_BYTES;
#pragma unroll
        for (int ks = 0; ks < 2; ks++) {
            const uint32_t kb = ks * 32;               // 16 halves
            uint32_t af[4][4], bf[8][2];
#pragma unroll
            for (int i = 0; i < 4; i++)
                ldsm_x4(af[i], as_s + kb + i * (16 * ROWB));
#pragma unroll
            for (int jj = 0; jj < 4; jj++)
                ldsm_x4(&bf[jj * 2][0], bs_s + kb + jj * (16 * ROWB));
#pragma unroll
            for (int i = 0; i < 4; i++)
#pragma unroll
                for (int j = 0; j < 8; j++)
                    mma_f16(acc[i][j], af[i], bf[j]);
        }
    }
#undef ISSUE_STAGE

    const int ar = lane >> 2;
    const int ac = lane & 3;

#pragma unroll
    for (int i = 0; i < 4; i++) {
        const int mrow0 = m0 + wm + i * 16 + ar;
#pragma unroll
        for (int j = 0; j < 8; j++) {
            const int n = n0 + wn + j * 8 + ac * 2;
            if (EPI == 0) {
                float* d0 = Co + (long)mrow0 * N + n;
                float* d1 = Co + (long)(mrow0 + 8) * N + n;
                *(float2*)d0 = make_float2(acc[i][j][0], acc[i][j][1]);
                *(float2*)d1 = make_float2(acc[i][j][2], acc[i][j][3]);
            } else {
                const int which = n >> 11;
                const int rem = n & 2047;
                const int h = rem >> 7, dd = rem & 127;
                __half* base = (which == 0) ? Cq : (which == 1) ? Ck : Cv;
                const int b0_ = mrow0 >> 11, t0 = mrow0 & 2047;
                const int b1_ = (mrow0 + 8) >> 11, t1 = (mrow0 + 8) & 2047;
                __half* d0 = base + (((long)(b0_ * Hp + h) * Tp + t0) * Dp + dd);
                __half* d1 = base + (((long)(b1_ * Hp + h) * Tp + t1) * Dp + dd);
                *(__half2*)d0 = __floats2half2_rn(acc[i][j][0], acc[i][j][1]);
                *(__half2*)d1 = __floats2half2_rn(acc[i][j][2], acc[i][j][3]);
            }
        }
    }
}

// ===========================================================================
// Tensor-core causal flash attention (fp16 m16n8k16, fp32 accum/softmax).
// Block: 128 queries, 8 warps (16 rows each). KV tile = 64, 2-stage cp.async.
// (unchanged from R15 — measured good)
// ===========================================================================
#define QS_STR 136
#define KV_STR 136
#define P_STR  72
#define KVSTG_BYTES (64*KV_STR*2)   // 17408
#define ATTN4_SMEM ((128*QS_STR + 2*64*KV_STR + 2*64*KV_STR + 8*16*P_STR) * 2)

__global__ void __launch_bounds__(256)
attn_tc(const __half* __restrict__ Qg, const __half* __restrict__ Kg,
        const __half* __restrict__ Vg, __half* __restrict__ Og)
{
    extern __shared__ __half sma[];
    __half* Qs = sma;                          // [128][136]
    __half* Ps = Qs + 128 * QS_STR + 4 * 64 * KV_STR;  // [8][16][72]

    const int tid = threadIdx.x;
    const int lane = tid & 31;
    const int w = tid >> 5;
    const int g = lane >> 2;
    const int t4 = lane & 3;
    const int qt = gridDim.x - 1 - blockIdx.x;   // heavy tiles first
    const int bh = blockIdx.y;
    const int q0 = qt * 128;
    const long base = (long)bh * Tp * Dp;
    __half* Pw = Ps + w * 16 * P_STR;

    const uint32_t qs_sm = (uint32_t)__cvta_generic_to_shared(Qs);
    const uint32_t ks_sm = qs_sm + 128 * QS_STR * 2;
    const uint32_t vs_sm = ks_sm + 2 * KVSTG_BYTES;
    const uint32_t ps_sm = (uint32_t)__cvta_generic_to_shared(Pw);

    // per-lane ldmatrix base addresses (stage 0)
    const uint32_t q_addr = qs_sm + (w * 16 + (lane & 15)) * (QS_STR * 2) + ((lane >> 4) << 4);
    const uint32_t k_addr = ks_sm + (((lane >> 4) << 3) + (lane & 7)) * (KV_STR * 2)
                                  + (((lane >> 3) & 1) << 4);
    const uint32_t p_addr = ps_sm + (lane & 15) * (P_STR * 2) + ((lane >> 4) << 4);
    const uint32_t v_addr = vs_sm + ((((lane >> 3) & 1) << 3) + (lane & 7)) * (KV_STR * 2)
                                  + ((lane >> 4) << 4);

    // KV tile cp.async: 8 chunks of 16B per thread (4 K + 4 V)
    const int kvr = tid >> 4;      // base row 0..15 (x4 via +16*i)
    const int kvc = tid & 15;      // 16B chunk in row

#define ISSUE_KV(st, jj) do {                                                \
        const __half* kg = Kg + base + (long)((jj) * 64 + kvr) * Dp + kvc * 8; \
        const __half* vg = Vg + base + (long)((jj) * 64 + kvr) * Dp + kvc * 8; \
        const uint32_t kx = ks_sm + (st) * KVSTG_BYTES + kvr * (KV_STR * 2) + kvc * 16; \
        const uint32_t vx = vs_sm + (st) * KVSTG_BYTES + kvr * (KV_STR * 2) + kvc * 16; \
        _Pragma("unroll")                                                    \
        for (int i_ = 0; i_ < 4; i_++) {                                     \
            cp16(kx + i_ * (16 * KV_STR * 2), kg + (long)(i_ * 16) * Dp);    \
            cp16(vx + i_ * (16 * KV_STR * 2), vg + (long)(i_ * 16) * Dp);    \
        }                                                                    \
        CP_COMMIT();                                                         \
    } while (0)

    // stage Q tile (half, direct copy)
    for (int i = tid; i < 128 * 16; i += 256) {
        int r = i >> 4, c8 = i & 15;
        *(uint4*)&Qs[r * QS_STR + c8 * 8] =
            *(const uint4*)(Qg + base + (long)(q0 + r) * Dp + c8 * 8);
    }

    float oacc[16][4];
#pragma unroll
    for (int i = 0; i < 16; i++)
#pragma unroll
        for (int q = 0; q < 4; q++) oacc[i][q] = 0.f;
    float m_lo = -1e30f, m_hi = -1e30f, l_lo = 0.f, l_hi = 0.f;

    const int row_lo = q0 + w * 16 + g;
    const int row_hi = row_lo + 8;
    const int njt = qt * 2 + 2;

    ISSUE_KV(0, 0);

    for (int j = 0; j < njt; j++) {
        const int s = j & 1;
        if (j + 1 < njt) {
            ISSUE_KV(s ^ 1, j + 1);
            CP_WAIT(1);
        } else {
            CP_WAIT(0);
        }
        __syncthreads();

        const uint32_t k_s = k_addr + s * KVSTG_BYTES;
        const uint32_t v_s = v_addr + s * KVSTG_BYTES;

        // ---- S = Q K^T (16 x 64), fp16 mma ----
        float sf[8][4];
#pragma unroll
        for (int n = 0; n < 8; n++)
#pragma unroll
            for (int q = 0; q < 4; q++) sf[n][q] = 0.f;

#pragma unroll
        for (int kc = 0; kc < 8; kc++) {
            uint32_t af[4], bf[8][2];
            ldsm_x4(af, q_addr + kc * 32);
#pragma unroll
            for (int jj = 0; jj < 4; jj++)
                ldsm_x4(&bf[jj * 2][0], k_s + jj * (16 * KV_STR * 2) + kc * 32);
#pragma unroll
            for (int n = 0; n < 8; n++)
                mma_f16(sf[n], af, bf[n]);
        }

        // ---- mask + scale ----
        if (j * 64 + 63 <= q0 + w * 16) {
#pragma unroll
            for (int n = 0; n < 8; n++)
#pragma unroll
                for (int q = 0; q < 4; q++) sf[n][q] *= SCALE;
        } else {
#pragma unroll
            for (int n = 0; n < 8; n++) {
                const int col = j * 64 + n * 8 + 2 * t4;
                sf[n][0] = (col     <= row_lo) ? sf[n][0] * SCALE : -1e30f;
                sf[n][1] = (col + 1 <= row_lo) ? sf[n][1] * SCALE : -1e30f;
                sf[n][2] = (col     <= row_hi) ? sf[n][2] * SCALE : -1e30f;
                sf[n][3] = (col + 1 <= row_hi) ? sf[n][3] * SCALE : -1e30f;
            }
        }

        // ---- online softmax (fp32 exp) ----
        float tl = -1e30f, th = -1e30f;
#pragma unroll
        for (int n = 0; n < 8; n++) {
            tl = fmaxf(tl, fmaxf(sf[n][0], sf[n][1]));
            th = fmaxf(th, fmaxf(sf[n][2], sf[n][3]));
        }
        tl = fmaxf(tl, __shfl_xor_sync(0xffffffffu, tl, 1));
        tl = fmaxf(tl, __shfl_xor_sync(0xffffffffu, tl, 2));
        th = fmaxf(th, __shfl_xor_sync(0xffffffffu, th, 1));
        th = fmaxf(th, __shfl_xor_sync(0xffffffffu, th, 2));
        const float mn_lo = fmaxf(m_lo, tl);
        const float mn_hi = fmaxf(m_hi, th);
        const float corr_lo = __expf(m_lo - mn_lo);
        const float corr_hi = __expf(m_hi - mn_hi);
        m_lo = mn_lo; m_hi = mn_hi;

        float sum_lo = 0.f, sum_hi = 0.f;
#pragma unroll
        for (int n = 0; n < 8; n++) {
            float p0 = __expf(sf[n][0] - m_lo);
            float p1 = __expf(sf[n][1] - m_lo);
            float p2 = __expf(sf[n][2] - m_hi);
            float p3 = __expf(sf[n][3] - m_hi);
            sum_lo += p0 + p1;
            sum_hi += p2 + p3;
            const int pc = n * 8 + 2 * t4;
            *(__half2*)&Pw[g * P_STR + pc]       = __floats2half2_rn(p0, p1);
            *(__half2*)&Pw[(g + 8) * P_STR + pc] = __floats2half2_rn(p2, p3);
        }
        sum_lo += __shfl_xor_sync(0xffffffffu, sum_lo, 1);
        sum_lo += __shfl_xor_sync(0xffffffffu, sum_lo, 2);
        sum_hi += __shfl_xor_sync(0xffffffffu, sum_hi, 1);
        sum_hi += __shfl_xor_sync(0xffffffffu, sum_hi, 2);
        l_lo = l_lo * corr_lo + sum_lo;
        l_hi = l_hi * corr_hi + sum_hi;
#pragma unroll
        for (int dt = 0; dt < 16; dt++) {
            oacc[dt][0] *= corr_lo; oacc[dt][1] *= corr_lo;
            oacc[dt][2] *= corr_hi; oacc[dt][3] *= corr_hi;
        }
        __syncwarp();

        // ---- O += P V (fp16 mma, V via ldmatrix.trans) ----
#pragma unroll
        for (int kc = 0; kc < 4; kc++) {
            uint32_t paf[4], vbf[16][2];
            ldsm_x4(paf, p_addr + kc * 32);
#pragma unroll
            for (int jj = 0; jj < 8; jj++)
                ldsm_x4_t(&vbf[jj * 2][0],
                          v_s + kc * (16 * KV_STR * 2) + jj * 32);
#pragma unroll
            for (int dt = 0; dt < 16; dt++)
                mma_f16(oacc[dt], paf, vbf[dt]);
        }
        __syncthreads();
    }

    // ---- epilogue: fp16 output for the proj GEMM ----
    const float il_lo = 1.f / l_lo;
    const float il_hi = 1.f / l_hi;
    const int b = bh >> 4, h = bh & 15;
    __half* o_lo = Og + ((long)(b * Tp + row_lo)) * Cp + h * Dp;
    __half* o_hi = Og + ((long)(b * Tp + row_hi)) * Cp + h * Dp;
#pragma unroll
    for (int dt = 0; dt < 16; dt++) {
        const int col = dt * 8 + 2 * t4;
        *(__half2*)(o_lo + col) = __floats2half2_rn(oacc[dt][0] * il_lo, oacc[dt][1] * il_lo);
        *(__half2*)(o_hi + col) = __floats2half2_rn(oacc[dt][2] * il_hi, oacc[dt][3] * il_hi);
    }
}

// ---------------------------------------------------------------------------
extern "C" void kernel_launch(void* const* d_in, const int* in_sizes, int n_in,
                              void* d_out, int out_size)
{
    const float* x      = (const float*)d_in[0];  // [B,T,C]
    const float* W_attn = (const float*)d_in[1];  // [3C,C]
    const float* W_proj = (const float*)d_in[2];  // [C,C]
    float* out = (float*)d_out;                   // [B,T,C]

    __half *pq, *pk, *pv, *pao, *pxh, *pwa, *pwp;
    cudaGetSymbolAddress((void**)&pq,  g_qh);
    cudaGetSymbolAddress((void**)&pk,  g_kh);
    cudaGetSymbolAddress((void**)&pv,  g_vh);
    cudaGetSymbolAddress((void**)&pao, g_aoh);
    cudaGetSymbolAddress((void**)&pxh, g_xh);
    cudaGetSymbolAddress((void**)&pwa, g_wah);
    cudaGetSymbolAddress((void**)&pwp, g_wph);

    cudaFuncSetAttribute(attn_tc,
                         cudaFuncAttributeMaxDynamicSharedMemorySize, ATTN4_SMEM);
    cudaFuncSetAttribute(gemm_mma<0>,
                         cudaFuncAttributeMaxDynamicSharedMemorySize, GEMM_SMEM);
    cudaFuncSetAttribute(gemm_mma<1>,
                         cudaFuncAttributeMaxDynamicSharedMemorySize, GEMM_SMEM);

    // 0) fp16 conversion pre-pass
    {
        int n4x = BTp * Cp / 4, n4a = 3 * Cp * Cp / 4, n4p = Cp * Cp / 4;
        cvt_f16_kernel<<<(n4x + 255) / 256, 256>>>((const float4*)x,      (__half2*)pxh, n4x);
        cvt_f16_kernel<<<(n4a + 255) / 256, 256>>>((const float4*)W_attn, (__half2*)pwa, n4a);
        cvt_f16_kernel<<<(n4p + 255) / 256, 256>>>((const float4*)W_proj, (__half2*)pwp, n4p);
    }
    // 1) QKV projection with fp16 scatter into [B,H,T,d]
    {
        dim3 grid(3 * Cp / BN, BTp / BM);
        gemm_mma<1><<<grid, 128, GEMM_SMEM>>>(pxh, pwa, nullptr, pq, pk, pv,
                                              BTp, 3 * Cp, Cp);
    }
    // 2) fp16 tensor-core causal flash attention -> g_aoh [B,T,C]
    {
        dim3 grid(Tp / 128, BHp);
        attn_tc<<<grid, 256, ATTN4_SMEM>>>(pq, pk, pv, pao);
    }
    // 3) output projection (fp32 output)
    {
        dim3 grid(Cp / BN, BTp / BM);
        gemm_mma<0><<<grid, 128, GEMM_SMEM>>>(pao, pwp, out, nullptr, nullptr, nullptr,
                                              BTp, Cp, Cp);
    }
}